// round 4
// baseline (speedup 1.0000x reference)
#include <cuda_runtime.h>

// Problem shape (fixed by dataset)
constexpr int B = 1024;
constexpr int O = 256;
constexpr int D = 1024;

// Tiling
constexpr int BM = 64;
constexpr int BN = 32;
constexpr int BK = 64;
constexpr int TM = 4;
constexpr int TN = 2;
constexpr int XP = BK + 4;  // 68 floats: even -> 8B-aligned rows for LDS.64
constexpr int BP = BK + 2;  // 66 floats: even row stride; 16 rows * 264B hit distinct bank pairs

constexpr float ALPHA = 0.005f;

using ull = unsigned long long;

__device__ __forceinline__ ull add_f32x2(ull a, ull b) {
    ull r; asm("add.rn.f32x2 %0, %1, %2;" : "=l"(r) : "l"(a), "l"(b)); return r;
}
__device__ __forceinline__ ull fma_f32x2(ull a, ull b, ull c) {
    ull r; asm("fma.rn.f32x2 %0, %1, %2, %3;" : "=l"(r) : "l"(a), "l"(b), "l"(c)); return r;
}

union F2U { ull u; float2 f; };

// Kernel 1: xd[b,o] = sum_d |x-c| + 0.5*sqrt(sum_d (x-c)^2)
__global__ __launch_bounds__(256, 1) void CDR_dist_kernel(
    const float* __restrict__ x,
    const float* __restrict__ basis,
    float* __restrict__ xd)
{
    __shared__ float xs[BM][XP];
    __shared__ float bs[BN][BP];   // holds NEGATED basis

    const int tid = threadIdx.x;
    const int tx  = tid & 15;
    const int ty  = tid >> 4;
    const int bm  = blockIdx.x * BM;
    const int bn  = blockIdx.y * BN;

    const ull ABSM = 0x7fffffff7fffffffULL;

    ull acc1[TM][TN];
    ull acc2[TM][TN];
#pragma unroll
    for (int i = 0; i < TM; i++)
#pragma unroll
        for (int j = 0; j < TN; j++) { acc1[i][j] = 0ULL; acc2[i][j] = 0ULL; }

    for (int k0 = 0; k0 < D; k0 += BK) {
        // x tile: 64x64 = 1024 float4, 4 per thread
#pragma unroll
        for (int t = 0; t < 4; t++) {
            int idx = tid + t * 256;
            int r = idx >> 4;
            int c = (idx & 15) << 2;
            float4 v = *reinterpret_cast<const float4*>(&x[(size_t)(bm + r) * D + k0 + c]);
            *reinterpret_cast<float4*>(&xs[r][c]) = v;
        }
        // basis tile: 32x64 = 512 float4, 2 per thread; store NEGATED
#pragma unroll
        for (int t = 0; t < 2; t++) {
            int idx = tid + t * 256;
            int r = idx >> 4;
            int c = (idx & 15) << 2;
            float4 v = *reinterpret_cast<const float4*>(&basis[(size_t)(bn + r) * D + k0 + c]);
            bs[r][c + 0] = -v.x;
            bs[r][c + 1] = -v.y;
            bs[r][c + 2] = -v.z;
            bs[r][c + 3] = -v.w;
        }
        __syncthreads();

#pragma unroll 8
        for (int k = 0; k < BK; k += 2) {
            ull xv[TM];
            ull bv[TN];
#pragma unroll
            for (int i = 0; i < TM; i++)
                xv[i] = *reinterpret_cast<const ull*>(&xs[ty * TM + i][k]);  // broadcast
#pragma unroll
            for (int j = 0; j < TN; j++)
                bv[j] = *reinterpret_cast<const ull*>(&bs[tx * TN + j][k]);  // conflict-free
#pragma unroll
            for (int i = 0; i < TM; i++)
#pragma unroll
                for (int j = 0; j < TN; j++) {
                    ull d = add_f32x2(xv[i], bv[j]);        // x + (-b), packed
                    acc1[i][j] = add_f32x2(acc1[i][j], d & ABSM);  // |d| via ALU-pipe AND
                    acc2[i][j] = fma_f32x2(d, d, acc2[i][j]);
                }
        }
        __syncthreads();
    }

#pragma unroll
    for (int i = 0; i < TM; i++)
#pragma unroll
        for (int j = 0; j < TN; j++) {
            F2U u1; u1.u = acc1[i][j];
            F2U u2; u2.u = acc2[i][j];
            float l1 = u1.f.x + u1.f.y;
            float l2 = u2.f.x + u2.f.y;
            int m = bm + ty * TM + i;
            int n = bn + tx * TN + j;
            xd[(size_t)m * O + n] = l1 + 0.5f * sqrtf(l2);
        }
}

// Kernel 2: in-place alpha correction + negation, one warp per row.
// out[b,o] = ALPHA*S - (1+ALPHA)*xd[b,o],  S = row sum.
__global__ __launch_bounds__(256, 1) void CDR_alpha_kernel(float* __restrict__ xd)
{
    const int warp = threadIdx.x >> 5;
    const int lane = threadIdx.x & 31;
    const int b = blockIdx.x * 8 + warp;

    float4* row = reinterpret_cast<float4*>(xd + (size_t)b * O);  // 64 float4 per row
    float4 v0 = row[lane];
    float4 v1 = row[lane + 32];

    float s = (v0.x + v0.y) + (v0.z + v0.w) + (v1.x + v1.y) + (v1.z + v1.w);
#pragma unroll
    for (int off = 16; off > 0; off >>= 1)
        s += __shfl_xor_sync(0xffffffffu, s, off);

    const float cs = ALPHA * s;
    const float cv = -(1.0f + ALPHA);
    v0.x = fmaf(cv, v0.x, cs); v0.y = fmaf(cv, v0.y, cs);
    v0.z = fmaf(cv, v0.z, cs); v0.w = fmaf(cv, v0.w, cs);
    v1.x = fmaf(cv, v1.x, cs); v1.y = fmaf(cv, v1.y, cs);
    v1.z = fmaf(cv, v1.z, cs); v1.w = fmaf(cv, v1.w, cs);
    row[lane]      = v0;
    row[lane + 32] = v1;
}

extern "C" void kernel_launch(void* const* d_in, const int* in_sizes, int n_in,
                              void* d_out, int out_size)
{
    const float* x     = (const float*)d_in[0];
    const float* basis = (const float*)d_in[1];
    float* out = (float*)d_out;

    dim3 grid1(B / BM, O / BN);   // 16 x 8 = 128 blocks
    CDR_dist_kernel<<<grid1, 256>>>(x, basis, out);
    CDR_alpha_kernel<<<B / 8, 256>>>(out);
}

// round 6
// speedup vs baseline: 1.0477x; 1.0477x over previous
#include <cuda_runtime.h>

// Problem shape (fixed by dataset)
constexpr int B = 1024;
constexpr int O = 256;
constexpr int D = 1024;

// Tiling
constexpr int BM = 64;
constexpr int BN = 32;
constexpr int BK = 64;
constexpr int TM = 4;
constexpr int TN = 2;
constexpr int XP  = BK + 4;  // xs row stride (floats): 68, rows 16B-aligned
constexpr int BTP = BN + 2;  // bs (transposed) row stride: 34, rows 8B-aligned (34*4=136=17*8)

constexpr float ALPHA = 0.005f;

// Per-row precomputed sums (sum and sum-of-squares)
__device__ float g_Sx[B];
__device__ float g_Qx[B];
__device__ float g_Sb[O];
__device__ float g_Qb[O];

// Kernel 0: per-row sum / sum-of-squares for x (1024 rows) and basis (256 rows).
// One warp per row, 1280 warps total.
__global__ __launch_bounds__(256, 2) void CDR_pre_kernel(
    const float* __restrict__ x, const float* __restrict__ basis)
{
    const int gwarp = (blockIdx.x * 256 + threadIdx.x) >> 5;
    const int lane  = threadIdx.x & 31;

    const float* row = (gwarp < B) ? (x + (size_t)gwarp * D)
                                   : (basis + (size_t)(gwarp - B) * D);
    const float4* r4 = reinterpret_cast<const float4*>(row);

    float s = 0.0f, q = 0.0f;
#pragma unroll
    for (int i = 0; i < D / 4 / 32; i++) {          // 8 iters
        float4 v = r4[lane + i * 32];
        s += (v.x + v.y) + (v.z + v.w);
        q = fmaf(v.x, v.x, q);
        q = fmaf(v.y, v.y, q);
        q = fmaf(v.z, v.z, q);
        q = fmaf(v.w, v.w, q);
    }
#pragma unroll
    for (int off = 16; off > 0; off >>= 1) {
        s += __shfl_xor_sync(0xffffffffu, s, off);
        q += __shfl_xor_sync(0xffffffffu, q, off);
    }
    if (lane == 0) {
        if (gwarp < B) { g_Sx[gwarp] = s; g_Qx[gwarp] = q; }
        else           { g_Sb[gwarp - B] = s; g_Qb[gwarp - B] = q; }
    }
}

// Kernel 1: accm = sum_d max(x,b)  (FMNMX on ALU pipe + FADD)
//           accd = sum_d x*b       (FFMA)
// then xd = (2*accm - Sx - Sb) + 0.5*sqrt(Qx - 2*accd + Qb)
__global__ __launch_bounds__(256, 1) void CDR_dist_kernel(
    const float* __restrict__ x,
    const float* __restrict__ basis,
    float* __restrict__ xd)
{
    __shared__ float xs[BM][XP];    // x tile, [m][k]
    __shared__ float bs[BK][BTP];   // basis tile TRANSPOSED, [k][n]

    const int tid = threadIdx.x;
    const int tx  = tid & 15;       // 16 threads across N
    const int ty  = tid >> 4;       // 16 threads across M
    const int bm  = blockIdx.x * BM;
    const int bn  = blockIdx.y * BN;

    float accm[TM][TN];
    float accd[TM][TN];
#pragma unroll
    for (int i = 0; i < TM; i++)
#pragma unroll
        for (int j = 0; j < TN; j++) { accm[i][j] = 0.0f; accd[i][j] = 0.0f; }

    for (int k0 = 0; k0 < D; k0 += BK) {
        // x tile: 64x64 = 1024 float4, 4 per thread, rows 16B-aligned -> STS.128
#pragma unroll
        for (int t = 0; t < 4; t++) {
            int idx = tid + t * 256;
            int r = idx >> 4;
            int c = (idx & 15) << 2;
            float4 v = *reinterpret_cast<const float4*>(&x[(size_t)(bm + r) * D + k0 + c]);
            *reinterpret_cast<float4*>(&xs[r][c]) = v;
        }
        // basis tile: 32x64 = 512 float4, 2 per thread, stored transposed [k][n]
#pragma unroll
        for (int t = 0; t < 2; t++) {
            int idx = tid + t * 256;
            int r = idx >> 4;          // n row (0..31)
            int c = (idx & 15) << 2;   // k col
            float4 v = *reinterpret_cast<const float4*>(&basis[(size_t)(bn + r) * D + k0 + c]);
            bs[c + 0][r] = v.x;
            bs[c + 1][r] = v.y;
            bs[c + 2][r] = v.z;
            bs[c + 3][r] = v.w;
        }
        __syncthreads();

#pragma unroll 4
        for (int kk = 0; kk < BK; kk += 2) {
            float2 xv[TM];
#pragma unroll
            for (int i = 0; i < TM; i++)
                xv[i] = *reinterpret_cast<const float2*>(&xs[ty * TM + i][kk]);   // broadcast
            float2 b0 = *reinterpret_cast<const float2*>(&bs[kk    ][tx * TN]);   // conflict-free
            float2 b1 = *reinterpret_cast<const float2*>(&bs[kk + 1][tx * TN]);
#pragma unroll
            for (int i = 0; i < TM; i++) {
                accm[i][0] += fmaxf(xv[i].x, b0.x);
                accd[i][0]  = fmaf (xv[i].x, b0.x, accd[i][0]);
                accm[i][1] += fmaxf(xv[i].x, b0.y);
                accd[i][1]  = fmaf (xv[i].x, b0.y, accd[i][1]);
                accm[i][0] += fmaxf(xv[i].y, b1.x);
                accd[i][0]  = fmaf (xv[i].y, b1.x, accd[i][0]);
                accm[i][1] += fmaxf(xv[i].y, b1.y);
                accd[i][1]  = fmaf (xv[i].y, b1.y, accd[i][1]);
            }
        }
        __syncthreads();
    }

#pragma unroll
    for (int i = 0; i < TM; i++) {
        int m = bm + ty * TM + i;
        float sx = g_Sx[m];
        float qx = g_Qx[m];
#pragma unroll
        for (int j = 0; j < TN; j++) {
            int n = bn + tx * TN + j;
            float l1  = 2.0f * accm[i][j] - sx - g_Sb[n];
            float l2s = qx - 2.0f * accd[i][j] + g_Qb[n];
            xd[(size_t)m * O + n] = l1 + 0.5f * sqrtf(fmaxf(l2s, 0.0f));
        }
    }
}

// Kernel 2: in-place alpha correction + negation, one warp per row.
// out[b,o] = ALPHA*S - (1+ALPHA)*xd[b,o],  S = row sum.
__global__ __launch_bounds__(128, 1) void CDR_alpha_kernel(float* __restrict__ xd)
{
    const int warp = threadIdx.x >> 5;
    const int lane = threadIdx.x & 31;
    const int b = blockIdx.x * 4 + warp;

    float4* row = reinterpret_cast<float4*>(xd + (size_t)b * O);  // 64 float4 per row
    float4 v0 = row[lane];
    float4 v1 = row[lane + 32];

    float s = (v0.x + v0.y) + (v0.z + v0.w) + (v1.x + v1.y) + (v1.z + v1.w);
#pragma unroll
    for (int off = 16; off > 0; off >>= 1)
        s += __shfl_xor_sync(0xffffffffu, s, off);

    const float cs = ALPHA * s;
    const float cv = -(1.0f + ALPHA);
    v0.x = fmaf(cv, v0.x, cs); v0.y = fmaf(cv, v0.y, cs);
    v0.z = fmaf(cv, v0.z, cs); v0.w = fmaf(cv, v0.w, cs);
    v1.x = fmaf(cv, v1.x, cs); v1.y = fmaf(cv, v1.y, cs);
    v1.z = fmaf(cv, v1.z, cs); v1.w = fmaf(cv, v1.w, cs);
    row[lane]      = v0;
    row[lane + 32] = v1;
}

extern "C" void kernel_launch(void* const* d_in, const int* in_sizes, int n_in,
                              void* d_out, int out_size)
{
    const float* x     = (const float*)d_in[0];
    const float* basis = (const float*)d_in[1];
    float* out = (float*)d_out;

    CDR_pre_kernel<<<(B + O) / 8, 256>>>(x, basis);
    dim3 grid1(B / BM, O / BN);   // 16 x 8 = 128 blocks
    CDR_dist_kernel<<<grid1, 256>>>(x, basis, out);
    CDR_alpha_kernel<<<B / 4, 128>>>(out);
}

// round 9
// speedup vs baseline: 1.0963x; 1.0464x over previous
#include <cuda_runtime.h>
#include <cuda_bf16.h>
#include <cstdint>

// Problem shape (fixed by dataset)
constexpr int B = 1024;
constexpr int O = 256;
constexpr int D = 1024;

// Tiling
constexpr int BM = 64;
constexpr int BN = 32;
constexpr int BK = 64;
constexpr int TM = 4;
constexpr int TN = 2;
constexpr int XP  = BK + 4;  // xs f32 row stride: 68 (rows 16B aligned, broadcast reads)
constexpr int BTP = BN + 2;  // bs f32 (transposed [k][n]) row stride: 34 (conflict-free float2)
constexpr int XH  = BK + 8;  // bf16 row stride: 72 -> 144B rows, +4 bank rotation, 16B-aligned

constexpr float ALPHA = 0.005f;

__device__ float g_Sx[B];
__device__ float g_Qx[B];
__device__ float g_Sb[O];
__device__ float g_Qb[O];

__device__ __forceinline__ void ldsm_x4(uint32_t& r0, uint32_t& r1, uint32_t& r2, uint32_t& r3,
                                        uint32_t addr) {
    asm volatile("ldmatrix.sync.aligned.m8n8.x4.shared.b16 {%0,%1,%2,%3}, [%4];"
                 : "=r"(r0), "=r"(r1), "=r"(r2), "=r"(r3) : "r"(addr));
}

__device__ __forceinline__ void mma_bf16(float d[4],
                                         uint32_t a0, uint32_t a1, uint32_t a2, uint32_t a3,
                                         uint32_t b0, uint32_t b1) {
    asm volatile(
        "mma.sync.aligned.m16n8k16.row.col.f32.bf16.bf16.f32 "
        "{%0,%1,%2,%3}, {%4,%5,%6,%7}, {%8,%9}, {%0,%1,%2,%3};"
        : "+f"(d[0]), "+f"(d[1]), "+f"(d[2]), "+f"(d[3])
        : "r"(a0), "r"(a1), "r"(a2), "r"(a3), "r"(b0), "r"(b1));
}

// Kernel 0: per-row sum/sum-sq; 2 warps per row for latency hiding.
__global__ __launch_bounds__(256, 2) void CDR_pre_kernel(
    const float* __restrict__ x, const float* __restrict__ basis)
{
    __shared__ float sP[8], qP[8];
    const int w    = threadIdx.x >> 5;          // warp 0-7
    const int lane = threadIdx.x & 31;
    const int row  = blockIdx.x * 4 + (w >> 1); // global row id (x rows then basis rows)
    const int half = w & 1;

    const float* rp = (row < B) ? (x + (size_t)row * D)
                                : (basis + (size_t)(row - B) * D);
    const float4* r4 = reinterpret_cast<const float4*>(rp) + half * 128;  // 512 floats per half

    float s = 0.0f, q = 0.0f;
#pragma unroll
    for (int i = 0; i < 4; i++) {               // 4 float4 per lane
        float4 v = r4[lane + i * 32];
        s += (v.x + v.y) + (v.z + v.w);
        q = fmaf(v.x, v.x, q);
        q = fmaf(v.y, v.y, q);
        q = fmaf(v.z, v.z, q);
        q = fmaf(v.w, v.w, q);
    }
#pragma unroll
    for (int off = 16; off > 0; off >>= 1) {
        s += __shfl_xor_sync(0xffffffffu, s, off);
        q += __shfl_xor_sync(0xffffffffu, q, off);
    }
    if (lane == 0) { sP[w] = s; qP[w] = q; }
    __syncthreads();
    if (threadIdx.x < 4) {
        int r = blockIdx.x * 4 + threadIdx.x;
        float S = sP[threadIdx.x * 2] + sP[threadIdx.x * 2 + 1];
        float Q = qP[threadIdx.x * 2] + qP[threadIdx.x * 2 + 1];
        if (r < B) { g_Sx[r] = S; g_Qx[r] = Q; }
        else       { g_Sb[r - B] = S; g_Qb[r - B] = Q; }
    }
}

// Kernel 1: scalar pipes compute accm = sum max(x,b); tensor pipe computes dot = x.b
// xd = (2*accm - Sx - Sb) + 0.5*sqrt(Qx - 2*dot + Qb)
__global__ __launch_bounds__(256, 1) void CDR_dist_kernel(
    const float* __restrict__ x,
    const float* __restrict__ basis,
    float* __restrict__ xd)
{
    __shared__ float xs[BM][XP];                 // f32 x tile [m][k]
    __shared__ float bs[BK][BTP];                // f32 basis tile transposed [k][n]
    __shared__ __nv_bfloat16 xh[BM][XH];         // bf16 x tile [m][k] (ldmatrix A)
    __shared__ __nv_bfloat16 bh[BN][XH];         // bf16 basis tile [n][k] (ldmatrix B)
    __shared__ float dots[BM][BN + 1];           // epilogue exchange

    const int tid  = threadIdx.x;
    const int lane = tid & 31;
    const int w    = tid >> 5;                   // warp 0-7
    const int wm   = w & 3;                      // warp M16 block (0-3)
    const int wn   = w >> 2;                     // warp N16 block (0-1)
    const int tx   = tid & 15;
    const int ty   = tid >> 4;
    const int bm   = blockIdx.x * BM;
    const int bn   = blockIdx.y * BN;

    // ldmatrix lane addresses (constant across chunks)
    const uint32_t xh_base = (uint32_t)__cvta_generic_to_shared(&xh[0][0]);
    const uint32_t bh_base = (uint32_t)__cvta_generic_to_shared(&bh[0][0]);
    const int a_row = wm * 16 + (lane & 15);
    const int a_col = (lane >> 4) * 8;
    const uint32_t a_addr = xh_base + (a_row * XH + a_col) * 2;
    const int b_row = wn * 16 + (lane & 7) + ((lane >> 4) << 3);
    const int b_col = ((lane >> 3) & 1) * 8;
    const uint32_t b_addr = bh_base + (b_row * XH + b_col) * 2;

    float accm[TM][TN];
#pragma unroll
    for (int i = 0; i < TM; i++)
#pragma unroll
        for (int j = 0; j < TN; j++) accm[i][j] = 0.0f;
    float dacc[2][4] = {};                       // two n8 mma tiles

    for (int k0 = 0; k0 < D; k0 += BK) {
        // x tile: 1024 float4, 4/thread -> f32 tile + bf16 tile
#pragma unroll
        for (int t = 0; t < 4; t++) {
            int idx = tid + t * 256;
            int r = idx >> 4;
            int c = (idx & 15) << 2;
            float4 v = *reinterpret_cast<const float4*>(&x[(size_t)(bm + r) * D + k0 + c]);
            *reinterpret_cast<float4*>(&xs[r][c]) = v;
            __nv_bfloat162 h0 = __floats2bfloat162_rn(v.x, v.y);
            __nv_bfloat162 h1 = __floats2bfloat162_rn(v.z, v.w);
            uint2 hp = make_uint2(*reinterpret_cast<uint32_t*>(&h0),
                                  *reinterpret_cast<uint32_t*>(&h1));
            *reinterpret_cast<uint2*>(&xh[r][c]) = hp;   // 8B aligned (144r + 2c, c%4==0)
        }
        // basis tile: 512 float4, 2/thread -> transposed f32 + bf16 [n][k]
#pragma unroll
        for (int t = 0; t < 2; t++) {
            int idx = tid + t * 256;
            int r = idx >> 4;          // n (0-31)
            int c = (idx & 15) << 2;   // k
            float4 v = *reinterpret_cast<const float4*>(&basis[(size_t)(bn + r) * D + k0 + c]);
            bs[c + 0][r] = v.x;
            bs[c + 1][r] = v.y;
            bs[c + 2][r] = v.z;
            bs[c + 3][r] = v.w;
            __nv_bfloat162 h0 = __floats2bfloat162_rn(v.x, v.y);
            __nv_bfloat162 h1 = __floats2bfloat162_rn(v.z, v.w);
            uint2 hp = make_uint2(*reinterpret_cast<uint32_t*>(&h0),
                                  *reinterpret_cast<uint32_t*>(&h1));
            *reinterpret_cast<uint2*>(&bh[r][c]) = hp;
        }
        __syncthreads();

        // Tensor path: 4 k16 steps per chunk, 2 mma per step
#pragma unroll
        for (int ks = 0; ks < 4; ks++) {
            uint32_t a0, a1, a2, a3, q0, q1, q2, q3;
            ldsm_x4(a0, a1, a2, a3, a_addr + ks * 32);
            ldsm_x4(q0, q1, q2, q3, b_addr + ks * 32);
            mma_bf16(dacc[0], a0, a1, a2, a3, q0, q1);
            mma_bf16(dacc[1], a0, a1, a2, a3, q2, q3);
        }

        // Scalar path: sum of max (FMNMX on alu + FADD on fma)
#pragma unroll 4
        for (int kk = 0; kk < BK; kk += 2) {
            float2 xv[TM];
#pragma unroll
            for (int i = 0; i < TM; i++)
                xv[i] = *reinterpret_cast<const float2*>(&xs[ty * TM + i][kk]);   // broadcast
            float2 b0 = *reinterpret_cast<const float2*>(&bs[kk    ][tx * TN]);   // conflict-free
            float2 b1 = *reinterpret_cast<const float2*>(&bs[kk + 1][tx * TN]);
#pragma unroll
            for (int i = 0; i < TM; i++) {
                accm[i][0] += fmaxf(xv[i].x, b0.x);
                accm[i][1] += fmaxf(xv[i].x, b0.y);
                accm[i][0] += fmaxf(xv[i].y, b1.x);
                accm[i][1] += fmaxf(xv[i].y, b1.y);
            }
        }
        __syncthreads();
    }

    // Exchange mma fragments through smem so dot aligns with scalar (m,n) mapping
    {
        int r0 = wm * 16 + (lane >> 2);
        int c0 = wn * 16 + (lane & 3) * 2;
#pragma unroll
        for (int t = 0; t < 2; t++) {
            dots[r0    ][c0 + t * 8    ] = dacc[t][0];
            dots[r0    ][c0 + t * 8 + 1] = dacc[t][1];
            dots[r0 + 8][c0 + t * 8    ] = dacc[t][2];
            dots[r0 + 8][c0 + t * 8 + 1] = dacc[t][3];
        }
    }
    __syncthreads();

#pragma unroll
    for (int i = 0; i < TM; i++) {
        int ml = ty * TM + i;
        int m  = bm + ml;
        float sx = g_Sx[m];
        float qx = g_Qx[m];
#pragma unroll
        for (int j = 0; j < TN; j++) {
            int nl = tx * TN + j;
            int n  = bn + nl;
            float dot = dots[ml][nl];
            float l1  = 2.0f * accm[i][j] - sx - g_Sb[n];
            float l2s = qx - 2.0f * dot + g_Qb[n];
            xd[(size_t)m * O + n] = l1 + 0.5f * sqrtf(fmaxf(l2s, 0.0f));
        }
    }
}

// Kernel 2: in-place alpha correction + negation, one warp per row.
__global__ __launch_bounds__(128, 1) void CDR_alpha_kernel(float* __restrict__ xd)
{
    const int warp = threadIdx.x >> 5;
    const int lane = threadIdx.x & 31;
    const int b = blockIdx.x * 4 + warp;

    float4* row = reinterpret_cast<float4*>(xd + (size_t)b * O);
    float4 v0 = row[lane];
    float4 v1 = row[lane + 32];

    float s = (v0.x + v0.y) + (v0.z + v0.w) + (v1.x + v1.y) + (v1.z + v1.w);
#pragma unroll
    for (int off = 16; off > 0; off >>= 1)
        s += __shfl_xor_sync(0xffffffffu, s, off);

    const float cs = ALPHA * s;
    const float cv = -(1.0f + ALPHA);
    v0.x = fmaf(cv, v0.x, cs); v0.y = fmaf(cv, v0.y, cs);
    v0.z = fmaf(cv, v0.z, cs); v0.w = fmaf(cv, v0.w, cs);
    v1.x = fmaf(cv, v1.x, cs); v1.y = fmaf(cv, v1.y, cs);
    v1.z = fmaf(cv, v1.z, cs); v1.w = fmaf(cv, v1.w, cs);
    row[lane]      = v0;
    row[lane + 32] = v1;
}

extern "C" void kernel_launch(void* const* d_in, const int* in_sizes, int n_in,
                              void* d_out, int out_size)
{
    const float* x     = (const float*)d_in[0];
    const float* basis = (const float*)d_in[1];
    float* out = (float*)d_out;

    CDR_pre_kernel<<<(B + O) / 4, 256>>>(x, basis);
    dim3 grid1(B / BM, O / BN);   // 16 x 8 = 128 blocks
    CDR_dist_kernel<<<grid1, 256>>>(x, basis, out);
    CDR_alpha_kernel<<<B / 4, 128>>>(out);
}

// round 10
// speedup vs baseline: 1.6000x; 1.4595x over previous
#include <cuda_runtime.h>
#include <cuda_fp16.h>
#include <cstdint>

// Problem shape (fixed by dataset)
constexpr int B = 1024;
constexpr int O = 256;
constexpr int D = 1024;

// Tiling
constexpr int BM = 64;
constexpr int BN = 32;
constexpr int BK = 64;
constexpr int TM = 4;
constexpr int TN = 2;
constexpr int XH  = BK + 8;   // fp16 tile row stride: 72 halves = 144B (ldmatrix-friendly, 16B aligned)
constexpr int BTW = BN + 2;   // bt row: 34 half2 = 136B (8B multiple)

constexpr float ALPHA = 0.005f;

__device__ __forceinline__ void ldsm_x4(uint32_t& r0, uint32_t& r1, uint32_t& r2, uint32_t& r3,
                                        uint32_t addr) {
    asm volatile("ldmatrix.sync.aligned.m8n8.x4.shared.b16 {%0,%1,%2,%3}, [%4];"
                 : "=r"(r0), "=r"(r1), "=r"(r2), "=r"(r3) : "r"(addr));
}

__device__ __forceinline__ void mma_f16(float d[4],
                                        uint32_t a0, uint32_t a1, uint32_t a2, uint32_t a3,
                                        uint32_t b0, uint32_t b1) {
    asm volatile(
        "mma.sync.aligned.m16n8k16.row.col.f32.f16.f16.f32 "
        "{%0,%1,%2,%3}, {%4,%5,%6,%7}, {%8,%9}, {%0,%1,%2,%3};"
        : "+f"(d[0]), "+f"(d[1]), "+f"(d[2]), "+f"(d[3])
        : "r"(a0), "r"(a1), "r"(a2), "r"(a3), "r"(b0), "r"(b1));
}

__device__ __forceinline__ __half2 u2h(uint32_t u) {
    return *reinterpret_cast<__half2*>(&u);
}

// Dist kernel: scalar pipes accumulate sum max(x,b) in fp16x2 (HMNMX2 alu + HADD2 fma),
// tensor pipe computes dot = x.b; row sums Sx,Qx,Sb,Qb computed in-kernel by the loaders.
// xd = (2*accm - Sx - Sb) + 0.5*sqrt(Qx - 2*dot + Qb)
__global__ __launch_bounds__(256, 1) void CDR_dist_kernel(
    const float* __restrict__ x,
    const float* __restrict__ basis,
    float* __restrict__ xd)
{
    __shared__ __half  xh[BM][XH];        // fp16 x tile [m][k]   (ldmatrix A + scalar x)
    __shared__ __half  bh[BN][XH];        // fp16 b tile [n][k]   (ldmatrix B)
    __shared__ __half2 bt[BK / 2][BTW];   // b k-pair-major: bt[k/2][n] = (b[n][k], b[n][k+1])
    __shared__ float dots[BM][BN + 1];    // mma fragment exchange
    __shared__ float sSx[BM], sQx[BM], sSb[BN], sQb[BN];

    const int tid  = threadIdx.x;
    const int lane = tid & 31;
    const int w    = tid >> 5;
    const int wm   = w & 3;
    const int wn   = w >> 2;
    const int tx   = tid & 15;
    const int ty   = tid >> 4;
    const int bm   = blockIdx.x * BM;
    const int bn   = blockIdx.y * BN;

    // ldmatrix lane addresses (same geometry as the verified bf16 version)
    const uint32_t xh_base = (uint32_t)__cvta_generic_to_shared(&xh[0][0]);
    const uint32_t bh_base = (uint32_t)__cvta_generic_to_shared(&bh[0][0]);
    const int a_row = wm * 16 + (lane & 15);
    const int a_col = (lane >> 4) * 8;
    const uint32_t a_addr = xh_base + (a_row * XH + a_col) * 2;
    const int b_row = wn * 16 + (lane & 7) + ((lane >> 4) << 3);
    const int b_col = ((lane >> 3) & 1) * 8;
    const uint32_t b_addr = bh_base + (b_row * XH + b_col) * 2;

    float accm[TM][TN];
#pragma unroll
    for (int i = 0; i < TM; i++)
#pragma unroll
        for (int j = 0; j < TN; j++) accm[i][j] = 0.0f;
    float dacc[2][4] = {};

    // per-thread partial row sums (loader-aligned rows)
    float sxa[4] = {}, qxa[4] = {};
    float sba[2] = {}, qba[2] = {};

    for (int k0 = 0; k0 < D; k0 += BK) {
        // x tile: 4 float4/thread; accumulate Sx/Qx partials; store fp16
#pragma unroll
        for (int t = 0; t < 4; t++) {
            int idx = tid + t * 256;
            int r = idx >> 4;
            int c = (idx & 15) << 2;
            float4 v = *reinterpret_cast<const float4*>(&x[(size_t)(bm + r) * D + k0 + c]);
            sxa[t] += (v.x + v.y) + (v.z + v.w);
            qxa[t] = fmaf(v.x, v.x, qxa[t]);
            qxa[t] = fmaf(v.y, v.y, qxa[t]);
            qxa[t] = fmaf(v.z, v.z, qxa[t]);
            qxa[t] = fmaf(v.w, v.w, qxa[t]);
            __half2 h0 = __floats2half2_rn(v.x, v.y);
            __half2 h1 = __floats2half2_rn(v.z, v.w);
            uint2 hp = make_uint2(*reinterpret_cast<uint32_t*>(&h0),
                                  *reinterpret_cast<uint32_t*>(&h1));
            *reinterpret_cast<uint2*>(&xh[r][c]) = hp;
        }
        // basis tile: 2 float4/thread; accumulate Sb/Qb; store fp16 [n][k] + k-pair tile
#pragma unroll
        for (int t = 0; t < 2; t++) {
            int idx = tid + t * 256;
            int r = idx >> 4;          // n (0..31)
            int c = (idx & 15) << 2;   // k
            float4 v = *reinterpret_cast<const float4*>(&basis[(size_t)(bn + r) * D + k0 + c]);
            sba[t] += (v.x + v.y) + (v.z + v.w);
            qba[t] = fmaf(v.x, v.x, qba[t]);
            qba[t] = fmaf(v.y, v.y, qba[t]);
            qba[t] = fmaf(v.z, v.z, qba[t]);
            qba[t] = fmaf(v.w, v.w, qba[t]);
            __half2 h0 = __floats2half2_rn(v.x, v.y);
            __half2 h1 = __floats2half2_rn(v.z, v.w);
            uint2 hp = make_uint2(*reinterpret_cast<uint32_t*>(&h0),
                                  *reinterpret_cast<uint32_t*>(&h1));
            *reinterpret_cast<uint2*>(&bh[r][c]) = hp;
            bt[(c >> 1)    ][r] = h0;
            bt[(c >> 1) + 1][r] = h1;
        }
        __syncthreads();

        // Tensor path: 4 k16 steps, 2 mma per step
#pragma unroll
        for (int ks = 0; ks < 4; ks++) {
            uint32_t a0, a1, a2, a3, q0, q1, q2, q3;
            ldsm_x4(a0, a1, a2, a3, a_addr + ks * 32);
            ldsm_x4(q0, q1, q2, q3, b_addr + ks * 32);
            mma_f16(dacc[0], a0, a1, a2, a3, q0, q1);
            mma_f16(dacc[1], a0, a1, a2, a3, q2, q3);
        }

        // Scalar path: fp16x2 max + add, flush to f32 every 16 k
#pragma unroll
        for (int g = 0; g < 4; g++) {
            __half2 acch[TM][TN];
#pragma unroll
            for (int i = 0; i < TM; i++)
#pragma unroll
                for (int j = 0; j < TN; j++) acch[i][j] = __half2half2(__ushort_as_half(0));
#pragma unroll
            for (int q = 0; q < 4; q++) {
                int kk = g * 16 + q * 4;
                uint2 P0 = *reinterpret_cast<const uint2*>(&bt[(kk >> 1)    ][tx * TN]);
                uint2 P1 = *reinterpret_cast<const uint2*>(&bt[(kk >> 1) + 1][tx * TN]);
                __half2 b0n0 = u2h(P0.x), b0n1 = u2h(P0.y);   // k..k+1 for n0, n1
                __half2 b1n0 = u2h(P1.x), b1n1 = u2h(P1.y);   // k+2..k+3
#pragma unroll
                for (int i = 0; i < TM; i++) {
                    uint2 X = *reinterpret_cast<const uint2*>(&xh[ty * TM + i][kk]);
                    __half2 x01 = u2h(X.x), x23 = u2h(X.y);
                    acch[i][0] = __hadd2(acch[i][0], __hmax2(x01, b0n0));
                    acch[i][1] = __hadd2(acch[i][1], __hmax2(x01, b0n1));
                    acch[i][0] = __hadd2(acch[i][0], __hmax2(x23, b1n0));
                    acch[i][1] = __hadd2(acch[i][1], __hmax2(x23, b1n1));
                }
            }
#pragma unroll
            for (int i = 0; i < TM; i++)
#pragma unroll
                for (int j = 0; j < TN; j++) {
                    float2 f = __half22float2(acch[i][j]);
                    accm[i][j] += f.x + f.y;
                }
        }
        __syncthreads();
    }

    // Reduce row sums across the 16 loader threads per row (half-warp xor shfl)
#pragma unroll
    for (int off = 1; off < 16; off <<= 1) {
#pragma unroll
        for (int t = 0; t < 4; t++) {
            sxa[t] += __shfl_xor_sync(0xffffffffu, sxa[t], off);
            qxa[t] += __shfl_xor_sync(0xffffffffu, qxa[t], off);
        }
#pragma unroll
        for (int t = 0; t < 2; t++) {
            sba[t] += __shfl_xor_sync(0xffffffffu, sba[t], off);
            qba[t] += __shfl_xor_sync(0xffffffffu, qba[t], off);
        }
    }
    if ((tid & 15) == 0) {
        int rb = tid >> 4;
#pragma unroll
        for (int t = 0; t < 4; t++) { sSx[rb + 16 * t] = sxa[t]; sQx[rb + 16 * t] = qxa[t]; }
#pragma unroll
        for (int t = 0; t < 2; t++) { sSb[rb + 16 * t] = sba[t]; sQb[rb + 16 * t] = qba[t]; }
    }

    // Exchange mma fragments (m16n8k16 C layout)
    {
        int r0 = wm * 16 + (lane >> 2);
        int c0 = wn * 16 + (lane & 3) * 2;
#pragma unroll
        for (int t = 0; t < 2; t++) {
            dots[r0    ][c0 + t * 8    ] = dacc[t][0];
            dots[r0    ][c0 + t * 8 + 1] = dacc[t][1];
            dots[r0 + 8][c0 + t * 8    ] = dacc[t][2];
            dots[r0 + 8][c0 + t * 8 + 1] = dacc[t][3];
        }
    }
    __syncthreads();

#pragma unroll
    for (int i = 0; i < TM; i++) {
        int ml = ty * TM + i;
        int m  = bm + ml;
        float sx = sSx[ml];
        float qx = sQx[ml];
#pragma unroll
        for (int j = 0; j < TN; j++) {
            int nl = tx * TN + j;
            int n  = bn + nl;
            float l1  = 2.0f * accm[i][j] - sx - sSb[nl];
            float l2s = qx - 2.0f * dots[ml][nl] + sQb[nl];
            xd[(size_t)m * O + n] = l1 + 0.5f * sqrtf(fmaxf(l2s, 0.0f));
        }
    }
}

// Alpha correction + negation, one warp per row.
__global__ __launch_bounds__(128, 1) void CDR_alpha_kernel(float* __restrict__ xd)
{
    const int warp = threadIdx.x >> 5;
    const int lane = threadIdx.x & 31;
    const int b = blockIdx.x * 4 + warp;

    float4* row = reinterpret_cast<float4*>(xd + (size_t)b * O);
    float4 v0 = row[lane];
    float4 v1 = row[lane + 32];

    float s = (v0.x + v0.y) + (v0.z + v0.w) + (v1.x + v1.y) + (v1.z + v1.w);
#pragma unroll
    for (int off = 16; off > 0; off >>= 1)
        s += __shfl_xor_sync(0xffffffffu, s, off);

    const float cs = ALPHA * s;
    const float cv = -(1.0f + ALPHA);
    v0.x = fmaf(cv, v0.x, cs); v0.y = fmaf(cv, v0.y, cs);
    v0.z = fmaf(cv, v0.z, cs); v0.w = fmaf(cv, v0.w, cs);
    v1.x = fmaf(cv, v1.x, cs); v1.y = fmaf(cv, v1.y, cs);
    v1.z = fmaf(cv, v1.z, cs); v1.w = fmaf(cv, v1.w, cs);
    row[lane]      = v0;
    row[lane + 32] = v1;
}

extern "C" void kernel_launch(void* const* d_in, const int* in_sizes, int n_in,
                              void* d_out, int out_size)
{
    const float* x     = (const float*)d_in[0];
    const float* basis = (const float*)d_in[1];
    float* out = (float*)d_out;

    dim3 grid1(B / BM, O / BN);   // 16 x 8 = 128 blocks, one per SM
    CDR_dist_kernel<<<grid1, 256>>>(x, basis, out);
    CDR_alpha_kernel<<<B / 4, 128>>>(out);
}

// round 11
// speedup vs baseline: 1.8418x; 1.1511x over previous
#include <cuda_runtime.h>
#include <cuda_fp16.h>
#include <cstdint>

// Problem shape (fixed by dataset)
constexpr int B = 1024;
constexpr int O = 256;
constexpr int D = 1024;

// Tiling
constexpr int BM = 64;
constexpr int BN = 32;
constexpr int BK = 64;
constexpr int TM = 4;
constexpr int TN = 2;
constexpr int XH  = BK + 8;   // fp16 tile row stride: 72 halves = 144B, 16B-aligned rows
constexpr int BQW = 68;       // btq row stride in uint32 (17 uint4 = 272B, 16B-aligned)

constexpr float ALPHA = 0.005f;
constexpr int NBLOCKS = (B / BM) * (O / BN);   // 128

// Grid barrier state (zero-init; g_count self-resets each launch, g_flag monotonic)
__device__ unsigned g_count = 0;
__device__ unsigned g_flag  = 0;

__device__ __forceinline__ void ldsm_x4(uint32_t& r0, uint32_t& r1, uint32_t& r2, uint32_t& r3,
                                        uint32_t addr) {
    asm volatile("ldmatrix.sync.aligned.m8n8.x4.shared.b16 {%0,%1,%2,%3}, [%4];"
                 : "=r"(r0), "=r"(r1), "=r"(r2), "=r"(r3) : "r"(addr));
}

__device__ __forceinline__ void mma_f16(float d[4],
                                        uint32_t a0, uint32_t a1, uint32_t a2, uint32_t a3,
                                        uint32_t b0, uint32_t b1) {
    asm volatile(
        "mma.sync.aligned.m16n8k16.row.col.f32.f16.f16.f32 "
        "{%0,%1,%2,%3}, {%4,%5,%6,%7}, {%8,%9}, {%0,%1,%2,%3};"
        : "+f"(d[0]), "+f"(d[1]), "+f"(d[2]), "+f"(d[3])
        : "r"(a0), "r"(a1), "r"(a2), "r"(a3), "r"(b0), "r"(b1));
}

__device__ __forceinline__ __half2 u2h(uint32_t u) {
    return *reinterpret_cast<__half2*>(&u);
}

__global__ __launch_bounds__(256, 1) void CDR_fused_kernel(
    const float* __restrict__ x,
    const float* __restrict__ basis,
    float* __restrict__ xd)
{
    __shared__ __half    xh[BM][XH];          // fp16 x tile [m][k] (ldmatrix A + scalar X)
    __shared__ __half    bh[BN][XH];          // fp16 b tile [n][k] (ldmatrix B)
    __shared__ uint32_t  btq[BK / 4][BQW];    // b packed: [kquad][npair*4 + slot]
    __shared__ float dots[BM][BN + 1];
    __shared__ float sSx[BM], sQx[BM], sSb[BN], sQb[BN];

    const int tid  = threadIdx.x;
    const int lane = tid & 31;
    const int w    = tid >> 5;
    const int wm   = w & 3;
    const int wn   = w >> 2;
    const int tx   = tid & 15;
    const int ty   = tid >> 4;
    const int bm   = blockIdx.x * BM;
    const int bn   = blockIdx.y * BN;

    const uint32_t xh_base = (uint32_t)__cvta_generic_to_shared(&xh[0][0]);
    const uint32_t bh_base = (uint32_t)__cvta_generic_to_shared(&bh[0][0]);
    const int a_row = wm * 16 + (lane & 15);
    const int a_col = (lane >> 4) * 8;
    const uint32_t a_addr = xh_base + (a_row * XH + a_col) * 2;
    const int b_row = wn * 16 + (lane & 7) + ((lane >> 4) << 3);
    const int b_col = ((lane >> 3) & 1) * 8;
    const uint32_t b_addr = bh_base + (b_row * XH + b_col) * 2;

    float accm[TM][TN];
#pragma unroll
    for (int i = 0; i < TM; i++)
#pragma unroll
        for (int j = 0; j < TN; j++) accm[i][j] = 0.0f;
    float dacc[2][4] = {};

    float sxa[4] = {}, qxa[4] = {};
    float sba[2] = {}, qba[2] = {};

    // Prefetch chunk 0
    float4 pvx[4], pvb[2];
#pragma unroll
    for (int t = 0; t < 4; t++) {
        int idx = tid + t * 256;
        pvx[t] = *reinterpret_cast<const float4*>(&x[(size_t)(bm + (idx >> 4)) * D + ((idx & 15) << 2)]);
    }
#pragma unroll
    for (int t = 0; t < 2; t++) {
        int idx = tid + t * 256;
        pvb[t] = *reinterpret_cast<const float4*>(&basis[(size_t)(bn + (idx >> 4)) * D + ((idx & 15) << 2)]);
    }

#pragma unroll 1
    for (int chunk = 0; chunk < D / BK; chunk++) {
        // Store prefetched chunk to smem (+ fp16 convert + row-sum accumulation)
#pragma unroll
        for (int t = 0; t < 4; t++) {
            int idx = tid + t * 256;
            int r = idx >> 4;
            int c = (idx & 15) << 2;
            float4 v = pvx[t];
            sxa[t] += (v.x + v.y) + (v.z + v.w);
            qxa[t] = fmaf(v.x, v.x, qxa[t]);
            qxa[t] = fmaf(v.y, v.y, qxa[t]);
            qxa[t] = fmaf(v.z, v.z, qxa[t]);
            qxa[t] = fmaf(v.w, v.w, qxa[t]);
            __half2 h0 = __floats2half2_rn(v.x, v.y);
            __half2 h1 = __floats2half2_rn(v.z, v.w);
            uint2 hp = make_uint2(*reinterpret_cast<uint32_t*>(&h0),
                                  *reinterpret_cast<uint32_t*>(&h1));
            *reinterpret_cast<uint2*>(&xh[r][c]) = hp;
        }
#pragma unroll
        for (int t = 0; t < 2; t++) {
            int idx = tid + t * 256;
            int r = idx >> 4;          // n (0..31)
            int c = (idx & 15) << 2;   // k
            float4 v = pvb[t];
            sba[t] += (v.x + v.y) + (v.z + v.w);
            qba[t] = fmaf(v.x, v.x, qba[t]);
            qba[t] = fmaf(v.y, v.y, qba[t]);
            qba[t] = fmaf(v.z, v.z, qba[t]);
            qba[t] = fmaf(v.w, v.w, qba[t]);
            __half2 h0 = __floats2half2_rn(v.x, v.y);
            __half2 h1 = __floats2half2_rn(v.z, v.w);
            uint2 hp = make_uint2(*reinterpret_cast<uint32_t*>(&h0),
                                  *reinterpret_cast<uint32_t*>(&h1));
            *reinterpret_cast<uint2*>(&bh[r][c]) = hp;
            int kq = c >> 2, p = r >> 1, s = r & 1;
            btq[kq][p * 4 + s]     = hp.x;   // (k, k+1)
            btq[kq][p * 4 + 2 + s] = hp.y;   // (k+2, k+3)
        }
        __syncthreads();

        // Prefetch next chunk (latency overlapped with compute below)
        if (chunk + 1 < D / BK) {
            int k0n = (chunk + 1) * BK;
#pragma unroll
            for (int t = 0; t < 4; t++) {
                int idx = tid + t * 256;
                pvx[t] = *reinterpret_cast<const float4*>(
                    &x[(size_t)(bm + (idx >> 4)) * D + k0n + ((idx & 15) << 2)]);
            }
#pragma unroll
            for (int t = 0; t < 2; t++) {
                int idx = tid + t * 256;
                pvb[t] = *reinterpret_cast<const float4*>(
                    &basis[(size_t)(bn + (idx >> 4)) * D + k0n + ((idx & 15) << 2)]);
            }
        }

        // Tensor path: 4 k16 steps, 2 mma per step
#pragma unroll
        for (int ks = 0; ks < 4; ks++) {
            uint32_t a0, a1, a2, a3, q0, q1, q2, q3;
            ldsm_x4(a0, a1, a2, a3, a_addr + ks * 32);
            ldsm_x4(q0, q1, q2, q3, b_addr + ks * 32);
            mma_f16(dacc[0], a0, a1, a2, a3, q0, q1);
            mma_f16(dacc[1], a0, a1, a2, a3, q2, q3);
        }

        // Scalar path: fp16x2 max+add, LDS.128 feeds, flush every 32 k
#pragma unroll
        for (int g = 0; g < 2; g++) {
            __half2 acch[TM][TN];
#pragma unroll
            for (int i = 0; i < TM; i++)
#pragma unroll
                for (int j = 0; j < TN; j++) acch[i][j] = __half2half2(__ushort_as_half(0));
#pragma unroll
            for (int h8 = 0; h8 < 4; h8++) {
                int kk = g * 32 + h8 * 8;
                uint4 Bq0 = *reinterpret_cast<const uint4*>(&btq[(kk >> 2)    ][tx * 4]);
                uint4 Bq1 = *reinterpret_cast<const uint4*>(&btq[(kk >> 2) + 1][tx * 4]);
#pragma unroll
                for (int i = 0; i < TM; i++) {
                    uint4 X = *reinterpret_cast<const uint4*>(&xh[ty * TM + i][kk]);
                    acch[i][0] = __hadd2(acch[i][0], __hmax2(u2h(X.x), u2h(Bq0.x)));
                    acch[i][1] = __hadd2(acch[i][1], __hmax2(u2h(X.x), u2h(Bq0.y)));
                    acch[i][0] = __hadd2(acch[i][0], __hmax2(u2h(X.y), u2h(Bq0.z)));
                    acch[i][1] = __hadd2(acch[i][1], __hmax2(u2h(X.y), u2h(Bq0.w)));
                    acch[i][0] = __hadd2(acch[i][0], __hmax2(u2h(X.z), u2h(Bq1.x)));
                    acch[i][1] = __hadd2(acch[i][1], __hmax2(u2h(X.z), u2h(Bq1.y)));
                    acch[i][0] = __hadd2(acch[i][0], __hmax2(u2h(X.w), u2h(Bq1.z)));
                    acch[i][1] = __hadd2(acch[i][1], __hmax2(u2h(X.w), u2h(Bq1.w)));
                }
            }
#pragma unroll
            for (int i = 0; i < TM; i++)
#pragma unroll
                for (int j = 0; j < TN; j++) {
                    float2 f = __half22float2(acch[i][j]);
                    accm[i][j] += f.x + f.y;
                }
        }
        __syncthreads();
    }

    // Row-sum reduction across 16 loader threads per row
#pragma unroll
    for (int off = 1; off < 16; off <<= 1) {
#pragma unroll
        for (int t = 0; t < 4; t++) {
            sxa[t] += __shfl_xor_sync(0xffffffffu, sxa[t], off);
            qxa[t] += __shfl_xor_sync(0xffffffffu, qxa[t], off);
        }
#pragma unroll
        for (int t = 0; t < 2; t++) {
            sba[t] += __shfl_xor_sync(0xffffffffu, sba[t], off);
            qba[t] += __shfl_xor_sync(0xffffffffu, qba[t], off);
        }
    }
    if ((tid & 15) == 0) {
        int rb = tid >> 4;
#pragma unroll
        for (int t = 0; t < 4; t++) { sSx[rb + 16 * t] = sxa[t]; sQx[rb + 16 * t] = qxa[t]; }
#pragma unroll
        for (int t = 0; t < 2; t++) { sSb[rb + 16 * t] = sba[t]; sQb[rb + 16 * t] = qba[t]; }
    }

    // mma fragment exchange (m16n8k16 C layout)
    {
        int r0 = wm * 16 + (lane >> 2);
        int c0 = wn * 16 + (lane & 3) * 2;
#pragma unroll
        for (int t = 0; t < 2; t++) {
            dots[r0    ][c0 + t * 8    ] = dacc[t][0];
            dots[r0    ][c0 + t * 8 + 1] = dacc[t][1];
            dots[r0 + 8][c0 + t * 8    ] = dacc[t][2];
            dots[r0 + 8][c0 + t * 8 + 1] = dacc[t][3];
        }
    }
    __syncthreads();

#pragma unroll
    for (int i = 0; i < TM; i++) {
        int ml = ty * TM + i;
        int m  = bm + ml;
        float sx = sSx[ml];
        float qx = sQx[ml];
#pragma unroll
        for (int j = 0; j < TN; j++) {
            int nl = tx * TN + j;
            int n  = bn + nl;
            float l1  = 2.0f * accm[i][j] - sx - sSb[nl];
            float l2s = qx - 2.0f * dots[ml][nl] + sQb[nl];
            xd[(size_t)m * O + n] = l1 + 0.5f * sqrtf(fmaxf(l2s, 0.0f));
        }
    }

    // ---- Grid barrier (all 128 blocks co-resident: 1 block/SM, 128 < 148 SMs) ----
    __threadfence();                 // make xd writes visible
    __syncthreads();                 // whole block done writing
    if (tid == 0) {
        unsigned f0 = atomicAdd(&g_flag, 0);     // phase before arrival (no one advances until all arrive)
        unsigned t  = atomicAdd(&g_count, 1);
        if (t == NBLOCKS - 1) {
            g_count = 0;                          // reset for next graph replay
            __threadfence();
            atomicAdd(&g_flag, 1);                // release (monotonic phase)
        } else {
            while (atomicAdd(&g_flag, 0) == f0) { __nanosleep(64); }
        }
    }
    __syncthreads();

    // ---- Alpha pass: out = ALPHA*S - (1+ALPHA)*xd, one warp per row ----
    {
        int bid = blockIdx.y * gridDim.x + blockIdx.x;   // 0..127
        int m   = bid * 8 + w;                            // 8 rows per block
        float4* row = reinterpret_cast<float4*>(xd + (size_t)m * O);
        float4 v0 = __ldcg(&row[lane]);
        float4 v1 = __ldcg(&row[lane + 32]);

        float s = (v0.x + v0.y) + (v0.z + v0.w) + (v1.x + v1.y) + (v1.z + v1.w);
#pragma unroll
        for (int off = 16; off > 0; off >>= 1)
            s += __shfl_xor_sync(0xffffffffu, s, off);

        const float cs = ALPHA * s;
        const float cv = -(1.0f + ALPHA);
        v0.x = fmaf(cv, v0.x, cs); v0.y = fmaf(cv, v0.y, cs);
        v0.z = fmaf(cv, v0.z, cs); v0.w = fmaf(cv, v0.w, cs);
        v1.x = fmaf(cv, v1.x, cs); v1.y = fmaf(cv, v1.y, cs);
        v1.z = fmaf(cv, v1.z, cs); v1.w = fmaf(cv, v1.w, cs);
        row[lane]      = v0;
        row[lane + 32] = v1;
    }
}

extern "C" void kernel_launch(void* const* d_in, const int* in_sizes, int n_in,
                              void* d_out, int out_size)
{
    const float* x     = (const float*)d_in[0];
    const float* basis = (const float*)d_in[1];
    float* out = (float*)d_out;

    dim3 grid(B / BM, O / BN);   // 16 x 8 = 128 blocks, all co-resident
    CDR_fused_kernel<<<grid, 256>>>(x, basis, out);
}